// round 11
// baseline (speedup 1.0000x reference)
#include <cuda_runtime.h>
#include <cstdint>

// Problem constants
#define CIN  32
#define COUT 64
#define HW   56
#define LTOT 3136      // 56*56
#define KTOT 288       // 32*3*3

// ---------------------------------------------------------------------------
// Scratch (__device__ globals only; no allocations anywhere)
// ---------------------------------------------------------------------------
__device__ float    g_wq[COUT * KTOT];
__device__ float    g_ypre[COUT * LTOT];
__device__ unsigned g_maxP, g_maxC, g_maxY;

// ---------------------------------------------------------------------------
// Threefry-2x32 (20 rounds) — exact JAX core
// ---------------------------------------------------------------------------
#define TF_ROUNDS(ROTL)                                   \
  unsigned ks2 = k0 ^ k1 ^ 0x1BD11BDAu;                   \
  unsigned x0 = c0 + k0, x1 = c1 + k1;                    \
  x0+=x1; x1=ROTL(x1,13); x1^=x0;                         \
  x0+=x1; x1=ROTL(x1,15); x1^=x0;                         \
  x0+=x1; x1=ROTL(x1,26); x1^=x0;                         \
  x0+=x1; x1=ROTL(x1, 6); x1^=x0;                         \
  x0+=k1; x1+=ks2+1u;                                     \
  x0+=x1; x1=ROTL(x1,17); x1^=x0;                         \
  x0+=x1; x1=ROTL(x1,29); x1^=x0;                         \
  x0+=x1; x1=ROTL(x1,16); x1^=x0;                         \
  x0+=x1; x1=ROTL(x1,24); x1^=x0;                         \
  x0+=ks2; x1+=k0+2u;                                     \
  x0+=x1; x1=ROTL(x1,13); x1^=x0;                         \
  x0+=x1; x1=ROTL(x1,15); x1^=x0;                         \
  x0+=x1; x1=ROTL(x1,26); x1^=x0;                         \
  x0+=x1; x1=ROTL(x1, 6); x1^=x0;                         \
  x0+=k0; x1+=k1+3u;                                      \
  x0+=x1; x1=ROTL(x1,17); x1^=x0;                         \
  x0+=x1; x1=ROTL(x1,29); x1^=x0;                         \
  x0+=x1; x1=ROTL(x1,16); x1^=x0;                         \
  x0+=x1; x1=ROTL(x1,24); x1^=x0;                         \
  x0+=k1; x1+=ks2+4u;                                     \
  x0+=x1; x1=ROTL(x1,13); x1^=x0;                         \
  x0+=x1; x1=ROTL(x1,15); x1^=x0;                         \
  x0+=x1; x1=ROTL(x1,26); x1^=x0;                         \
  x0+=x1; x1=ROTL(x1, 6); x1^=x0;                         \
  x0+=ks2; x1+=k0+5u;                                     \
  *o0 = x0; *o1 = x1;

#define DROTL(x,d) __funnelshift_l((x),(x),(d))
#define HROTL(x,d) ((((x) << (d)) | ((x) >> (32 - (d)))))

__device__ __forceinline__ void dev_tf(unsigned k0, unsigned k1,
                                       unsigned c0, unsigned c1,
                                       unsigned* o0, unsigned* o1) {
  TF_ROUNDS(DROTL)
}

static void host_tf(unsigned k0, unsigned k1, unsigned c0, unsigned c1,
                    unsigned* o0, unsigned* o1) {
  TF_ROUNDS(HROTL)
}

// scale = max/127 + 1e-12, exact f32 ops
__device__ __forceinline__ float mk_scale(unsigned maxbits) {
  return __fadd_rn(__fdiv_rn(__uint_as_float(maxbits), 127.0f), 1e-12f);
}

// ---------------------------------------------------------------------------
// _bitflip_fi forward value for one element at flat index `idx`.
//   u   = fold(threefry(keyU, (0,idx)))  -> uniform [0,1)
//   pos = fold(threefry(keyP, (0,idx))) & 7  (only needed when flipping)
// fold = out0 ^ out1 (jax partitionable 32-bit random_bits)
// ---------------------------------------------------------------------------
__device__ __forceinline__ float fi_elem(float v, float scale,
                                         unsigned ua0, unsigned ua1,
                                         unsigned pb0, unsigned pb1,
                                         unsigned idx) {
  float r = rintf(__fdiv_rn(v, scale));          // round-half-even, IEEE div
  r = fminf(fmaxf(r, -128.0f), 127.0f);
  int q  = (int)r;
  int qt = q & 255;                              // two's complement 8-bit view
  unsigned b0, b1;
  dev_tf(ua0, ua1, 0u, idx, &b0, &b1);
  unsigned fb = b0 ^ b1;
  float u = __fsub_rn(__uint_as_float((fb >> 9) | 0x3f800000u), 1.0f);
  if (u < 0.008f) {                              // ber*bits, f32-rounded const
    unsigned p0, p1;
    dev_tf(pb0, pb1, 0u, idx, &p0, &p1);
    qt ^= (1 << (int)((p0 ^ p1) & 7u));
  }
  int qs = (qt >= 128) ? (qt - 256) : qt;
  return __fmul_rn(__int2float_rn(qs), scale);
}

// ---------------------------------------------------------------------------
// Per-(co,l): FI'd products into buf[0..287], then exact
// jax.lax.associative_scan tree (cumsum lowering on GPU) in place.
// Level sizes 288,144,72,36,18,9,4,2,1 -> 574 floats total.
// ---------------------------------------------------------------------------
__device__ __constant__ int c_off[9] = {0, 288, 432, 504, 540, 558, 567, 571, 573};
__device__ __constant__ int c_sz [9] = {288, 144, 72, 36, 18, 9, 4, 2, 1};

__device__ void compute_c(const float* __restrict__ x, int co, int l,
                          float scaleP,
                          unsigned ua0, unsigned ua1,
                          unsigned pb0, unsigned pb1,
                          float* buf) {
  const int oy = l / HW, ox = l - oy * HW;
  const unsigned base = ((unsigned)(co * LTOT + l)) * (unsigned)KTOT;

  #pragma unroll 1
  for (int ci = 0; ci < CIN; ci++) {
    #pragma unroll
    for (int dy = 0; dy < 3; dy++) {
      const int iy = oy + dy - 1;
      const bool vy = ((unsigned)iy < (unsigned)HW);
      #pragma unroll
      for (int dx = 0; dx < 3; dx++) {
        const int ix = ox + dx - 1;
        const int k = ci * 9 + dy * 3 + dx;
        float xv = 0.0f;
        if (vy && (unsigned)ix < (unsigned)HW)
          xv = __ldg(x + (ci * HW + iy) * HW + ix);
        const float w = g_wq[co * KTOT + k];
        const float p = __fmul_rn(xv, w);
        buf[k] = fi_elem(p, scaleP, ua0, ua1, pb0, pb1, base + (unsigned)k);
      }
    }
  }

  // down-sweep: pairwise sums per level
  #pragma unroll 1
  for (int lev = 0; lev < 8; lev++) {
    const int n = c_sz[lev], o = c_off[lev], o2 = c_off[lev + 1];
    for (int i = 0; i < n / 2; i++)
      buf[o2 + i] = __fadd_rn(buf[o + 2 * i], buf[o + 2 * i + 1]);
  }
  // up-sweep: level lev+1 already holds its own scan (in place)
  #pragma unroll 1
  for (int lev = 7; lev >= 0; lev--) {
    const int n = c_sz[lev], o = c_off[lev], o2 = c_off[lev + 1];
    for (int i = 0; i < n / 2; i++) {
      const float od = buf[o2 + i];
      if (2 * i + 2 < n) buf[o + 2 * i + 2] = __fadd_rn(od, buf[o + 2 * i + 2]);
      buf[o + 2 * i + 1] = od;
    }
  }
  // buf[0..287] now holds c[k] (exact cumsum tree)
}

// ---------------------------------------------------------------------------
// Kernels
// ---------------------------------------------------------------------------
__global__ void k_init() { g_maxP = 0u; g_maxC = 0u; g_maxY = 0u; }

__global__ void k_quant_w(const float* __restrict__ w) {
  __shared__ float sm[256];
  float m = 0.0f;
  for (int i = threadIdx.x; i < COUT * KTOT; i += 256)
    m = fmaxf(m, fabsf(w[i]));
  sm[threadIdx.x] = m;
  __syncthreads();
  for (int s = 128; s > 0; s >>= 1) {
    if (threadIdx.x < s) sm[threadIdx.x] = fmaxf(sm[threadIdx.x], sm[threadIdx.x + s]);
    __syncthreads();
  }
  const float scale = __fadd_rn(__fdiv_rn(sm[0], 127.0f), 1e-12f);
  for (int i = threadIdx.x; i < COUT * KTOT; i += 256) {
    float r = rintf(__fdiv_rn(w[i], scale));
    r = fminf(fmaxf(r, -128.0f), 127.0f);
    g_wq[i] = __fmul_rn(r, scale);   // _quant_ste keeps float (no int cast)
  }
}

// max|p| = max_k fl(max_l|xcol[l,k]| * max_co|wq[co,k]|)  (exact: RN monotone)
__global__ void k_maxp(const float* __restrict__ x) {
  __shared__ float sm[128];
  const int k = blockIdx.x;
  const int ci = k / 9, rr = k - ci * 9, dy = rr / 3, dx = rr - dy * 3;
  float mx = 0.0f;
  for (int l = threadIdx.x; l < LTOT; l += 128) {
    const int oy = l / HW, ox = l - oy * HW;
    const int iy = oy + dy - 1, ix = ox + dx - 1;
    if ((unsigned)iy < (unsigned)HW && (unsigned)ix < (unsigned)HW)
      mx = fmaxf(mx, fabsf(x[(ci * HW + iy) * HW + ix]));
  }
  sm[threadIdx.x] = mx;
  __syncthreads();
  for (int s = 64; s > 0; s >>= 1) {
    if (threadIdx.x < s) sm[threadIdx.x] = fmaxf(sm[threadIdx.x], sm[threadIdx.x + s]);
    __syncthreads();
  }
  if (threadIdx.x == 0) {
    float mw = 0.0f;
    for (int co = 0; co < COUT; co++)
      mw = fmaxf(mw, fabsf(g_wq[co * KTOT + k]));
    atomicMax(&g_maxP, __float_as_uint(__fmul_rn(sm[0], mw)));
  }
}

__global__ void k_maxc(const float* __restrict__ x,
                       unsigned ua0, unsigned ua1, unsigned pb0, unsigned pb1) {
  const int l  = blockIdx.x * 64 + threadIdx.x;   // grid.x = 49 -> exact
  const int co = blockIdx.y;
  const float scaleP = mk_scale(g_maxP);
  float buf[574];
  compute_c(x, co, l, scaleP, ua0, ua1, pb0, pb1, buf);
  float mc = 0.0f;
  #pragma unroll 1
  for (int k = 0; k < KTOT; k++) mc = fmaxf(mc, fabsf(buf[k]));
  unsigned m = __reduce_max_sync(0xffffffffu, __float_as_uint(mc));
  if ((threadIdx.x & 31) == 0) atomicMax(&g_maxC, m);
}

__global__ void k_y(const float* __restrict__ x,
                    unsigned pa0, unsigned pa1, unsigned pb0, unsigned pb1,
                    unsigned ca0, unsigned ca1, unsigned cb0, unsigned cb1) {
  const int l  = blockIdx.x * 64 + threadIdx.x;
  const int co = blockIdx.y;
  const float scaleP = mk_scale(g_maxP);
  const float scaleC = mk_scale(g_maxC);
  float buf[574];
  compute_c(x, co, l, scaleP, pa0, pa1, pb0, pb1, buf);

  const unsigned base = ((unsigned)(co * LTOT + l)) * (unsigned)KTOT;
  float acc = 0.0f, ysum = 0.0f;
  #pragma unroll 1
  for (int k = 1; k < KTOT; k++) {                 // k=0 is unused by output
    const float c  = buf[k];
    const float cf = fi_elem(c, scaleC, ca0, ca1, cb0, cb1, base + (unsigned)k);
    if (k == KTOT - 1) ysum = cf;                  // y_sum = c_fi[..., -1]
    else               acc  = __fadd_rn(acc, __fsub_rn(cf, c)); // (c_fi-c)[1:-1]
  }
  const float y = __fadd_rn(ysum, acc);
  g_ypre[co * LTOT + l] = y;
  unsigned m = __reduce_max_sync(0xffffffffu, __float_as_uint(fabsf(y)));
  if ((threadIdx.x & 31) == 0) atomicMax(&g_maxY, m);
}

__global__ void k_out(float* __restrict__ out,
                      unsigned ua0, unsigned ua1, unsigned pb0, unsigned pb1) {
  const int i = blockIdx.x * 256 + threadIdx.x;   // 784*256 = 200704 exact
  const float scaleY = mk_scale(g_maxY);
  out[i] = fi_elem(g_ypre[i], scaleY, ua0, ua1, pb0, pb1, (unsigned)i);
}

// ---------------------------------------------------------------------------
// Launch: derive all JAX subkeys on the host (pure integer math), 6 launches.
//   root = key(42) = (0,42)
//   K1,K2,K3 = split(root,3) foldlike: Kj = TF(root,(0,j))
//   For FI(key): kU = TF(key,(0,0)); kR = TF(key,(0,1));
//                randint lower-bits key = TF(kR,(0,1))
// ---------------------------------------------------------------------------
extern "C" void kernel_launch(void* const* d_in, const int* in_sizes, int n_in,
                              void* d_out, int out_size) {
  const float* x = (const float*)d_in[0];
  const float* w = (const float*)d_in[1];
  if (n_in >= 2 && in_sizes[0] == COUT * KTOT) {  // tolerate swapped order
    const float* t = x; x = w; w = t;
  }

  unsigned K1a, K1b, K2a, K2b, K3a, K3b;
  host_tf(0u, 42u, 0u, 0u, &K1a, &K1b);
  host_tf(0u, 42u, 0u, 1u, &K2a, &K2b);
  host_tf(0u, 42u, 0u, 2u, &K3a, &K3b);

  unsigned A1a, A1b, R1a, R1b, P1a, P1b;   // p-FI: uniform key, pos key
  host_tf(K1a, K1b, 0u, 0u, &A1a, &A1b);
  host_tf(K1a, K1b, 0u, 1u, &R1a, &R1b);
  host_tf(R1a, R1b, 0u, 1u, &P1a, &P1b);

  unsigned A2a, A2b, R2a, R2b, P2a, P2b;   // c-FI
  host_tf(K2a, K2b, 0u, 0u, &A2a, &A2b);
  host_tf(K2a, K2b, 0u, 1u, &R2a, &R2b);
  host_tf(R2a, R2b, 0u, 1u, &P2a, &P2b);

  unsigned A3a, A3b, R3a, R3b, P3a, P3b;   // y-FI
  host_tf(K3a, K3b, 0u, 0u, &A3a, &A3b);
  host_tf(K3a, K3b, 0u, 1u, &R3a, &R3b);
  host_tf(R3a, R3b, 0u, 1u, &P3a, &P3b);

  k_init<<<1, 1>>>();
  k_quant_w<<<1, 256>>>(w);
  k_maxp<<<KTOT, 128>>>(x);
  k_maxc<<<dim3(49, COUT), 64>>>(x, A1a, A1b, P1a, P1b);
  k_y<<<dim3(49, COUT), 64>>>(x, A1a, A1b, P1a, P1b, A2a, A2b, P2a, P2b);
  k_out<<<784, 256>>>((float*)d_out, A3a, A3b, P3a, P3b);
  (void)out_size;
}

// round 12
// speedup vs baseline: 1.0151x; 1.0151x over previous
#include <cuda_runtime.h>
#include <cstdint>

// Problem constants
#define CIN  32
#define COUT 64
#define HW   56
#define LTOT 3136      // 56*56
#define KTOT 288       // 32*3*3

// ---------------------------------------------------------------------------
// Scratch (__device__ globals only; no allocations anywhere)
// ---------------------------------------------------------------------------
__device__ float    g_wq[COUT * KTOT];
__device__ float    g_ypre[COUT * LTOT];
__device__ unsigned g_maxP, g_maxC, g_maxY;

// ---------------------------------------------------------------------------
// Threefry-2x32 (20 rounds) — exact JAX core
// ---------------------------------------------------------------------------
#define TF_ROUNDS(ROTL)                                   \
  unsigned ks2 = k0 ^ k1 ^ 0x1BD11BDAu;                   \
  unsigned x0 = c0 + k0, x1 = c1 + k1;                    \
  x0+=x1; x1=ROTL(x1,13); x1^=x0;                         \
  x0+=x1; x1=ROTL(x1,15); x1^=x0;                         \
  x0+=x1; x1=ROTL(x1,26); x1^=x0;                         \
  x0+=x1; x1=ROTL(x1, 6); x1^=x0;                         \
  x0+=k1; x1+=ks2+1u;                                     \
  x0+=x1; x1=ROTL(x1,17); x1^=x0;                         \
  x0+=x1; x1=ROTL(x1,29); x1^=x0;                         \
  x0+=x1; x1=ROTL(x1,16); x1^=x0;                         \
  x0+=x1; x1=ROTL(x1,24); x1^=x0;                         \
  x0+=ks2; x1+=k0+2u;                                     \
  x0+=x1; x1=ROTL(x1,13); x1^=x0;                         \
  x0+=x1; x1=ROTL(x1,15); x1^=x0;                         \
  x0+=x1; x1=ROTL(x1,26); x1^=x0;                         \
  x0+=x1; x1=ROTL(x1, 6); x1^=x0;                         \
  x0+=k0; x1+=k1+3u;                                      \
  x0+=x1; x1=ROTL(x1,17); x1^=x0;                         \
  x0+=x1; x1=ROTL(x1,29); x1^=x0;                         \
  x0+=x1; x1=ROTL(x1,16); x1^=x0;                         \
  x0+=x1; x1=ROTL(x1,24); x1^=x0;                         \
  x0+=k1; x1+=ks2+4u;                                     \
  x0+=x1; x1=ROTL(x1,13); x1^=x0;                         \
  x0+=x1; x1=ROTL(x1,15); x1^=x0;                         \
  x0+=x1; x1=ROTL(x1,26); x1^=x0;                         \
  x0+=x1; x1=ROTL(x1, 6); x1^=x0;                         \
  x0+=ks2; x1+=k0+5u;                                     \
  *o0 = x0; *o1 = x1;

#define DROTL(x,d) __funnelshift_l((x),(x),(d))
#define HROTL(x,d) ((((x) << (d)) | ((x) >> (32 - (d)))))

__device__ __forceinline__ void dev_tf(unsigned k0, unsigned k1,
                                       unsigned c0, unsigned c1,
                                       unsigned* o0, unsigned* o1) {
  TF_ROUNDS(DROTL)
}

static void host_tf(unsigned k0, unsigned k1, unsigned c0, unsigned c1,
                    unsigned* o0, unsigned* o1) {
  TF_ROUNDS(HROTL)
}

// scale = max/127 + 1e-12, exact f32 ops
__device__ __forceinline__ float mk_scale(unsigned maxbits) {
  return __fadd_rn(__fdiv_rn(__uint_as_float(maxbits), 127.0f), 1e-12f);
}

// ---------------------------------------------------------------------------
// _bitflip_fi forward value for one element at flat index `idx`.
//   u   = fold(threefry(keyU, (0,idx)))  -> uniform [0,1)
//   pos = fold(threefry(keyP, (0,idx))) & 7  (only needed when flipping)
// fold = out0 ^ out1 (jax partitionable 32-bit random_bits)
// ---------------------------------------------------------------------------
__device__ __forceinline__ float fi_elem(float v, float scale,
                                         unsigned ua0, unsigned ua1,
                                         unsigned pb0, unsigned pb1,
                                         unsigned idx) {
  float r = rintf(__fdiv_rn(v, scale));          // round-half-even, IEEE div
  r = fminf(fmaxf(r, -128.0f), 127.0f);
  int q  = (int)r;
  int qt = q & 255;                              // two's complement 8-bit view
  unsigned b0, b1;
  dev_tf(ua0, ua1, 0u, idx, &b0, &b1);
  unsigned fb = b0 ^ b1;
  float u = __fsub_rn(__uint_as_float((fb >> 9) | 0x3f800000u), 1.0f);
  if (u < 0.008f) {                              // ber*bits, f32-rounded const
    unsigned p0, p1;
    dev_tf(pb0, pb1, 0u, idx, &p0, &p1);
    qt ^= (1 << (int)((p0 ^ p1) & 7u));
  }
  int qs = (qt >= 128) ? (qt - 256) : qt;
  return __fmul_rn(__int2float_rn(qs), scale);
}

// ---------------------------------------------------------------------------
// Per-(co,l): FI'd products into buf[0..287], then exact
// jax.lax.associative_scan tree (cumsum lowering on GPU) in place.
// Level sizes 288,144,72,36,18,9,4,2,1 -> 574 floats total.
// ---------------------------------------------------------------------------
__device__ __constant__ int c_off[9] = {0, 288, 432, 504, 540, 558, 567, 571, 573};
__device__ __constant__ int c_sz [9] = {288, 144, 72, 36, 18, 9, 4, 2, 1};

__device__ void compute_c(const float* __restrict__ x, int co, int l,
                          float scaleP,
                          unsigned ua0, unsigned ua1,
                          unsigned pb0, unsigned pb1,
                          float* buf) {
  const int oy = l / HW, ox = l - oy * HW;
  const unsigned base = ((unsigned)(co * LTOT + l)) * (unsigned)KTOT;

  #pragma unroll 1
  for (int ci = 0; ci < CIN; ci++) {
    #pragma unroll
    for (int dy = 0; dy < 3; dy++) {
      const int iy = oy + dy - 1;
      const bool vy = ((unsigned)iy < (unsigned)HW);
      #pragma unroll
      for (int dx = 0; dx < 3; dx++) {
        const int ix = ox + dx - 1;
        const int k = ci * 9 + dy * 3 + dx;
        float xv = 0.0f;
        if (vy && (unsigned)ix < (unsigned)HW)
          xv = __ldg(x + (ci * HW + iy) * HW + ix);
        const float w = g_wq[co * KTOT + k];
        const float p = __fmul_rn(xv, w);
        buf[k] = fi_elem(p, scaleP, ua0, ua1, pb0, pb1, base + (unsigned)k);
      }
    }
  }

  // down-sweep: pairwise sums per level
  #pragma unroll 1
  for (int lev = 0; lev < 8; lev++) {
    const int n = c_sz[lev], o = c_off[lev], o2 = c_off[lev + 1];
    for (int i = 0; i < n / 2; i++)
      buf[o2 + i] = __fadd_rn(buf[o + 2 * i], buf[o + 2 * i + 1]);
  }
  // up-sweep: level lev+1 already holds its own scan (in place)
  #pragma unroll 1
  for (int lev = 7; lev >= 0; lev--) {
    const int n = c_sz[lev], o = c_off[lev], o2 = c_off[lev + 1];
    for (int i = 0; i < n / 2; i++) {
      const float od = buf[o2 + i];
      if (2 * i + 2 < n) buf[o + 2 * i + 2] = __fadd_rn(od, buf[o + 2 * i + 2]);
      buf[o + 2 * i + 1] = od;
    }
  }
  // buf[0..287] now holds c[k] (exact cumsum tree)
}

// ---------------------------------------------------------------------------
// Kernels
// ---------------------------------------------------------------------------
__global__ void k_init() { g_maxP = 0u; g_maxC = 0u; g_maxY = 0u; }

__global__ void k_quant_w(const float* __restrict__ w) {
  __shared__ float sm[256];
  float m = 0.0f;
  for (int i = threadIdx.x; i < COUT * KTOT; i += 256)
    m = fmaxf(m, fabsf(w[i]));
  sm[threadIdx.x] = m;
  __syncthreads();
  for (int s = 128; s > 0; s >>= 1) {
    if (threadIdx.x < s) sm[threadIdx.x] = fmaxf(sm[threadIdx.x], sm[threadIdx.x + s]);
    __syncthreads();
  }
  const float scale = __fadd_rn(__fdiv_rn(sm[0], 127.0f), 1e-12f);
  for (int i = threadIdx.x; i < COUT * KTOT; i += 256) {
    float r = rintf(__fdiv_rn(w[i], scale));
    r = fminf(fmaxf(r, -128.0f), 127.0f);
    g_wq[i] = __fmul_rn(r, scale);   // _quant_ste keeps float (no int cast)
  }
}

// max|p| = max_k fl(max_l|xcol[l,k]| * max_co|wq[co,k]|)  (exact: RN monotone)
__global__ void k_maxp(const float* __restrict__ x) {
  __shared__ float sm[128];
  const int k = blockIdx.x;
  const int ci = k / 9, rr = k - ci * 9, dy = rr / 3, dx = rr - dy * 3;
  float mx = 0.0f;
  for (int l = threadIdx.x; l < LTOT; l += 128) {
    const int oy = l / HW, ox = l - oy * HW;
    const int iy = oy + dy - 1, ix = ox + dx - 1;
    if ((unsigned)iy < (unsigned)HW && (unsigned)ix < (unsigned)HW)
      mx = fmaxf(mx, fabsf(x[(ci * HW + iy) * HW + ix]));
  }
  sm[threadIdx.x] = mx;
  __syncthreads();
  for (int s = 64; s > 0; s >>= 1) {
    if (threadIdx.x < s) sm[threadIdx.x] = fmaxf(sm[threadIdx.x], sm[threadIdx.x + s]);
    __syncthreads();
  }
  if (threadIdx.x == 0) {
    float mw = 0.0f;
    for (int co = 0; co < COUT; co++)
      mw = fmaxf(mw, fabsf(g_wq[co * KTOT + k]));
    atomicMax(&g_maxP, __float_as_uint(__fmul_rn(sm[0], mw)));
  }
}

__global__ void k_maxc(const float* __restrict__ x,
                       unsigned ua0, unsigned ua1, unsigned pb0, unsigned pb1) {
  const int l  = blockIdx.x * 64 + threadIdx.x;   // grid.x = 49 -> exact
  const int co = blockIdx.y;
  const float scaleP = mk_scale(g_maxP);
  float buf[574];
  compute_c(x, co, l, scaleP, ua0, ua1, pb0, pb1, buf);
  float mc = 0.0f;
  #pragma unroll 1
  for (int k = 0; k < KTOT; k++) mc = fmaxf(mc, fabsf(buf[k]));
  unsigned m = __reduce_max_sync(0xffffffffu, __float_as_uint(mc));
  if ((threadIdx.x & 31) == 0) atomicMax(&g_maxC, m);
}

__global__ void k_y(const float* __restrict__ x,
                    unsigned pa0, unsigned pa1, unsigned pb0, unsigned pb1,
                    unsigned ca0, unsigned ca1, unsigned cb0, unsigned cb1) {
  const int l  = blockIdx.x * 64 + threadIdx.x;
  const int co = blockIdx.y;
  const float scaleP = mk_scale(g_maxP);
  const float scaleC = mk_scale(g_maxC);
  float buf[574];
  compute_c(x, co, l, scaleP, pa0, pa1, pb0, pb1, buf);

  const unsigned base = ((unsigned)(co * LTOT + l)) * (unsigned)KTOT;
  float acc = 0.0f, ysum = 0.0f;
  #pragma unroll 1
  for (int k = 1; k < KTOT; k++) {                 // k=0 is unused by output
    const float c  = buf[k];
    const float cf = fi_elem(c, scaleC, ca0, ca1, cb0, cb1, base + (unsigned)k);
    if (k == KTOT - 1) ysum = cf;                  // y_sum = c_fi[..., -1]
    else               acc  = __fadd_rn(acc, __fsub_rn(cf, c)); // (c_fi-c)[1:-1]
  }
  const float y = __fadd_rn(ysum, acc);
  g_ypre[co * LTOT + l] = y;
  unsigned m = __reduce_max_sync(0xffffffffu, __float_as_uint(fabsf(y)));
  if ((threadIdx.x & 31) == 0) atomicMax(&g_maxY, m);
}

__global__ void k_out(float* __restrict__ out,
                      unsigned ua0, unsigned ua1, unsigned pb0, unsigned pb1) {
  const int i = blockIdx.x * 256 + threadIdx.x;   // 784*256 = 200704 exact
  const float scaleY = mk_scale(g_maxY);
  out[i] = fi_elem(g_ypre[i], scaleY, ua0, ua1, pb0, pb1, (unsigned)i);
}

// ---------------------------------------------------------------------------
// Launch: derive all JAX subkeys on the host (pure integer math), 6 launches.
//   root = key(42) = (0,42)
//   K1,K2,K3 = split(root,3) foldlike: Kj = TF(root,(0,j))
//   For FI(key): kU = TF(key,(0,0)); kR = TF(key,(0,1));
//                randint lower-bits key = TF(kR,(0,1))
// ---------------------------------------------------------------------------
extern "C" void kernel_launch(void* const* d_in, const int* in_sizes, int n_in,
                              void* d_out, int out_size) {
  const float* x = (const float*)d_in[0];
  const float* w = (const float*)d_in[1];
  if (n_in >= 2 && in_sizes[0] == COUT * KTOT) {  // tolerate swapped order
    const float* t = x; x = w; w = t;
  }

  unsigned K1a, K1b, K2a, K2b, K3a, K3b;
  host_tf(0u, 42u, 0u, 0u, &K1a, &K1b);
  host_tf(0u, 42u, 0u, 1u, &K2a, &K2b);
  host_tf(0u, 42u, 0u, 2u, &K3a, &K3b);

  unsigned A1a, A1b, R1a, R1b, P1a, P1b;   // p-FI: uniform key, pos key
  host_tf(K1a, K1b, 0u, 0u, &A1a, &A1b);
  host_tf(K1a, K1b, 0u, 1u, &R1a, &R1b);
  host_tf(R1a, R1b, 0u, 1u, &P1a, &P1b);

  unsigned A2a, A2b, R2a, R2b, P2a, P2b;   // c-FI
  host_tf(K2a, K2b, 0u, 0u, &A2a, &A2b);
  host_tf(K2a, K2b, 0u, 1u, &R2a, &R2b);
  host_tf(R2a, R2b, 0u, 1u, &P2a, &P2b);

  unsigned A3a, A3b, R3a, R3b, P3a, P3b;   // y-FI
  host_tf(K3a, K3b, 0u, 0u, &A3a, &A3b);
  host_tf(K3a, K3b, 0u, 1u, &R3a, &R3b);
  host_tf(R3a, R3b, 0u, 1u, &P3a, &P3b);

  k_init<<<1, 1>>>();
  k_quant_w<<<1, 256>>>(w);
  k_maxp<<<KTOT, 128>>>(x);
  k_maxc<<<dim3(49, COUT), 64>>>(x, A1a, A1b, P1a, P1b);
  k_y<<<dim3(49, COUT), 64>>>(x, A1a, A1b, P1a, P1b, A2a, A2b, P2a, P2b);
  k_out<<<784, 256>>>((float*)d_out, A3a, A3b, P3a, P3b);
  (void)out_size;
}